// round 14
// baseline (speedup 1.0000x reference)
#include <cuda_runtime.h>
#include <cstdint>

// Problem constants: D=64, K=1024, N=65536.
#define DIM   64
#define RPT   256        // rows per CTA (1 per thread)
#define CAP   16         // candidate buffer entries per row
#define KMAX  1024

__device__ float g_c2[KMAX];       // ||w_k||^2, exact sequential fp32 chain
__device__ float g_l1w[KMAX];      // ||w_k||_1 (inflated)
__device__ float g_wmx[KMAX];      // max|w_k|
__device__ float g_stat[2];        // [0]=swmax (global max|W|), [1]=max_k l1w
__device__ int   g_wq[KMAX * 16];  // packed int8 codebook (4 per int32)

__device__ __forceinline__ int dp4a(int a, int b, int c) {
    int d;
    asm("dp4a.s32.s32 %0, %1, %2, %3;" : "=r"(d) : "r"(a), "r"(b), "r"(c));
    return d;
}

// ---------------------------------------------------------------------------
// prepA: per-code stats. c2 uses the exact sequential (mul, add) chain.
// ---------------------------------------------------------------------------
__global__ void prepA(const float* __restrict__ W, int K) {
    int k = blockIdx.x * blockDim.x + threadIdx.x;
    if (k >= K) return;
    const float* w = W + k * DIM;
    float c2 = 0.f, l1 = 0.f, mx = 0.f;
#pragma unroll
    for (int d = 0; d < DIM; ++d) {
        float v = w[d];
        c2 = __fadd_rn(c2, __fmul_rn(v, v));
        float a = fabsf(v);
        l1 += a;
        mx = fmaxf(mx, a);
    }
    g_c2[k]  = c2;
    g_l1w[k] = l1 * 1.0001f + 1e-12f;
    g_wmx[k] = mx;
}

// ---------------------------------------------------------------------------
// prepB: reduce per-code stats to global scalars (one CTA).
// ---------------------------------------------------------------------------
__global__ void prepB(int K) {
    __shared__ float sm[256], sl[256];
    int t = threadIdx.x;
    float mx = 0.f, l1m = 0.f;
    for (int k = t; k < K; k += 256) {
        mx  = fmaxf(mx, g_wmx[k]);
        l1m = fmaxf(l1m, g_l1w[k]);
    }
    sm[t] = mx; sl[t] = l1m;
    __syncthreads();
    for (int s = 128; s > 0; s >>= 1) {
        if (t < s) { sm[t] = fmaxf(sm[t], sm[t + s]); sl[t] = fmaxf(sl[t], sl[t + s]); }
        __syncthreads();
    }
    if (t == 0) { g_stat[0] = fmaxf(sm[0], 1e-30f); g_stat[1] = sl[0]; }
}

// ---------------------------------------------------------------------------
// prepC: quantize W to int8 with the global scale (deterministic rn).
// ---------------------------------------------------------------------------
__global__ void prepC(const float* __restrict__ W, int K) {
    int k = blockIdx.x * blockDim.x + threadIdx.x;
    if (k >= K) return;
    float s127 = 127.f / g_stat[0];
    const float* w = W + k * DIM;
#pragma unroll
    for (int i = 0; i < 16; ++i) {
        int p = 0;
#pragma unroll
        for (int b = 0; b < 4; ++b) {
            int q = __float2int_rn(w[i * 4 + b] * s127);
            q = max(-127, min(127, q));
            p |= (q & 0xff) << (8 * b);
        }
        g_wq[k * 16 + i] = p;
    }
}

// ---------------------------------------------------------------------------
// Main kernel: whole int8 codebook resident in smem; dp4a filter with cached
// threshold; rare exact fp32 rescore (bit-identical to reference chain).
// One row per thread; codes scanned ascending; candidates buffered in order.
// ---------------------------------------------------------------------------
__global__ void __launch_bounds__(256, 2)
vq_main(const float* __restrict__ X, const float* __restrict__ W,
        float* __restrict__ outQ, float* __restrict__ outI, int K)
{
    extern __shared__ char smem[];
    int*   wqs = (int*)smem;                           // [K][16] int   65536 B
    float* c2s = (float*)(smem + KMAX * 64);           // [K]            4096 B
    unsigned short* buf =
        (unsigned short*)(smem + KMAX * 64 + KMAX * 4); // [256][CAP]    8192 B

    const int tid = threadIdx.x;
    const int row = blockIdx.x * RPT + tid;

    // ---- stage whole int8 codebook + c2 into smem (once) ----
    {
        const int4* qsrc = (const int4*)g_wq;
        int4* qdst = (int4*)wqs;
#pragma unroll
        for (int i = 0; i < 16; ++i) qdst[tid + 256 * i] = qsrc[tid + 256 * i];
#pragma unroll
        for (int i = 0; i < 4; ++i) c2s[tid + 256 * i] = g_c2[tid + 256 * i];
    }

    // ---- load x row into registers ----
    float xr[DIM];
    {
        const float4* src = (const float4*)(X + (size_t)row * DIM);
#pragma unroll
        for (int q = 0; q < 16; ++q) {
            float4 v = src[q];
            xr[q * 4 + 0] = v.x; xr[q * 4 + 1] = v.y;
            xr[q * 4 + 2] = v.z; xr[q * 4 + 3] = v.w;
        }
    }

    // ---- exact L2 chain (reference rounding) ----
    float l2r = 0.f;
#pragma unroll
    for (int d = 0; d < DIM; ++d)
        l2r = __fadd_rn(l2r, __fmul_rn(xr[d], xr[d]));

    // ---- row stats for the rigorous filter window (verbatim R13) ----
    float sx = 0.f, l1x = 0.f;
#pragma unroll
    for (int d = 0; d < DIM; ++d) { float a = fabsf(xr[d]); sx = fmaxf(sx, a); l1x += a; }
    sx = fmaxf(sx, 1e-30f);
    const float sw = g_stat[0], l1wmax = g_stat[1];
    const float invsx = sx * (1.f / 127.f), invsw = sw * (1.f / 127.f);
    const float dxm = 0.6f * invsx + 4e-6f * sx;
    const float dwm = 0.6f * invsw + 4e-6f * sw;
    const float c2max = 64.f * sw * sw;
    const float window = 1.5f * (2.f * (dxm * l1wmax + dwm * (l1x * 1.0001f + 64.f * dxm))
                                 + c2max + 1e-6f);
    const float F2 = 2.f * invsx * invsw;
    int Wint = (int)ceilf(window / F2) + 2;
    if (Wint > (1 << 28)) Wint = 1 << 28;

    // ---- quantize x to packed int8 ----
    const float s127x = 127.f / sx;
    int xp[16];
#pragma unroll
    for (int i = 0; i < 16; ++i) {
        int p = 0;
#pragma unroll
        for (int b = 0; b < 4; ++b) {
            int q = __float2int_rn(xr[i * 4 + b] * s127x);
            q = max(-127, min(127, q));
            p |= (q & 0xff) << (8 * b);
        }
        xp[i] = p;
    }

    __syncthreads();   // codebook staged

    float bd = 3.4e38f;
    int   bi = 0;
    int   runmax = -(1 << 29);
    int   thresh = runmax - Wint;     // cached; updated only on candidate hits
    int   cnt = 0;

#define RESCORE(JL) do {                                                     \
        const float* wr_ = W + (size_t)(JL) * DIM;                           \
        float cl_ = 0.f;                                                     \
        _Pragma("unroll")                                                    \
        for (int d_ = 0; d_ < DIM; ++d_)                                     \
            cl_ = __fmaf_rn(xr[d_], __ldg(wr_ + d_), cl_);                   \
        float de_ = __fadd_rn(__fsub_rn(l2r, __fmul_rn(2.f, cl_)),           \
                              c2s[JL]);                                      \
        if (de_ < bd) { bd = de_; bi = (JL); }                               \
    } while (0)

    // ---- hot loop: 1024 codes, no syncs; cached-threshold filter ----
    const int* wp = wqs;
#pragma unroll 4
    for (int j = 0; j < KMAX; ++j, wp += 16) {
        const int4* wq4 = (const int4*)wp;             // broadcast LDS
        int4 a0 = wq4[0], a1 = wq4[1], a2 = wq4[2], a3 = wq4[3];
        int da = 0, db = 0, dc = 0, dd = 0;
        da = dp4a(xp[0],  a0.x, da); db = dp4a(xp[1],  a0.y, db);
        dc = dp4a(xp[2],  a0.z, dc); dd = dp4a(xp[3],  a0.w, dd);
        da = dp4a(xp[4],  a1.x, da); db = dp4a(xp[5],  a1.y, db);
        dc = dp4a(xp[6],  a1.z, dc); dd = dp4a(xp[7],  a1.w, dd);
        da = dp4a(xp[8],  a2.x, da); db = dp4a(xp[9],  a2.y, db);
        dc = dp4a(xp[10], a2.z, dc); dd = dp4a(xp[11], a2.w, dd);
        da = dp4a(xp[12], a3.x, da); db = dp4a(xp[13], a3.y, db);
        dc = dp4a(xp[14], a3.z, dc); dd = dp4a(xp[15], a3.w, dd);
        int doti = (da + db) + (dc + dd);
        if (doti >= thresh) {                          // rare
            runmax = max(runmax, doti);
            thresh = runmax - Wint;
            if (cnt == CAP) {                          // flush in order (rarer)
                for (int i = 0; i < cnt; ++i) { int jl = buf[tid * CAP + i]; RESCORE(jl); }
                cnt = 0;
            }
            buf[tid * CAP + cnt] = (unsigned short)j;
            ++cnt;
        }
    }

    // ---- deferred exact rescores (ascending order => first-index ties) ----
    for (int i = 0; i < cnt; ++i) { int jl = buf[tid * CAP + i]; RESCORE(jl); }
#undef RESCORE

    // ---- outputs ----
    if (outI) outI[row] = (float)bi;
    if (outQ) {
        const float4* src = (const float4*)(W + (size_t)bi * DIM);
        float4* dst = (float4*)(outQ + (size_t)row * DIM);
#pragma unroll
        for (int q = 0; q < 16; ++q) dst[q] = __ldg(src + q);
    }
}

// ---------------------------------------------------------------------------
extern "C" void kernel_launch(void* const* d_in, const int* in_sizes, int n_in,
                              void* d_out, int out_size) {
    const float* X = (const float*)d_in[0];
    const float* W = (const float*)d_in[1];
    int N = in_sizes[0] / DIM;
    int K = in_sizes[1] / DIM;

    long long nd = (long long)N * DIM;
    float* outQ = nullptr;
    float* outI = nullptr;
    if ((long long)out_size >= nd + N) { outQ = (float*)d_out; outI = (float*)d_out + nd; }
    else if ((long long)out_size == nd) { outQ = (float*)d_out; }
    else { outI = (float*)d_out; }

    const int smembytes = KMAX * 64 + KMAX * 4 + RPT * CAP * 2;   // 77824 B
    cudaFuncSetAttribute(vq_main, cudaFuncAttributeMaxDynamicSharedMemorySize,
                         smembytes);

    prepA<<<(K + 255) / 256, 256>>>(W, K);
    prepB<<<1, 256>>>(K);
    prepC<<<(K + 255) / 256, 256>>>(W, K);
    vq_main<<<N / RPT, 256, smembytes>>>(X, W, outQ, outI, K);
}

// round 15
// speedup vs baseline: 1.1688x; 1.1688x over previous
#include <cuda_runtime.h>
#include <cstdint>

// Problem constants: D=64, K=1024, N=65536.
#define DIM   64
#define NT    128        // codes per tile
#define RPT   256        // rows per CTA (2 per thread, 128 threads)
#define CAP   12         // candidate buffer entries per row
#define KMAX  1024
#define WSTR  68         // wsf row stride in floats (bank-spread, 16B aligned)

__device__ float g_c2[KMAX];   // ||w_k||^2, exact sequential fp32 chain
__device__ float g_stat[2];    // [0]=swmax (global max|W|), [1]=max_k l1w

__device__ __forceinline__ int dp4a(int a, int b, int c) {
    int d;
    asm("dp4a.s32.s32 %0, %1, %2, %3;" : "=r"(d) : "r"(a), "r"(b), "r"(c));
    return d;
}

// ---------------------------------------------------------------------------
// prep: one CTA. Per-code exact c2 (sequential mul,add chain) + global stats.
// ---------------------------------------------------------------------------
__global__ void prep_kernel(const float* __restrict__ W, int K) {
    __shared__ float sm[1024], sl[1024];
    int k = threadIdx.x;
    float c2 = 0.f, l1 = 0.f, mx = 0.f;
    if (k < K) {
        const float* w = W + k * DIM;
#pragma unroll
        for (int d = 0; d < DIM; ++d) {
            float v = w[d];
            c2 = __fadd_rn(c2, __fmul_rn(v, v));
            float a = fabsf(v);
            l1 += a;
            mx = fmaxf(mx, a);
        }
        g_c2[k] = c2;
    }
    sm[k] = mx; sl[k] = l1 * 1.0001f + 1e-12f;
    __syncthreads();
    for (int s = 512; s > 0; s >>= 1) {
        if (k < s) { sm[k] = fmaxf(sm[k], sm[k + s]); sl[k] = fmaxf(sl[k], sl[k + s]); }
        __syncthreads();
    }
    if (k == 0) { g_stat[0] = fmaxf(sm[0], 1e-30f); g_stat[1] = sl[0]; }
}

// ---------------------------------------------------------------------------
// Main kernel: 2 rows/thread; tiled int8/dp4a filter with double-buffered W
// fragments; rare exact fp32 rescore (bit-identical to reference chain).
// ---------------------------------------------------------------------------
__global__ void __launch_bounds__(128)
vq_main(const float* __restrict__ X, const float* __restrict__ W,
        float* __restrict__ outQ, float* __restrict__ outI, int K)
{
    extern __shared__ char smem[];
    float* wsf = (float*)smem;                                   // [128][WSTR] 34816 B
    int*   wqs = (int*)(smem + NT * WSTR * 4);                   // [129][16]    8256 B
    float* c2s = (float*)(smem + NT * WSTR * 4 + 129 * 64);      // [128]         512 B
    unsigned short* buf =
        (unsigned short*)(smem + NT * WSTR * 4 + 129 * 64 + 512); // [256][CAP]  6144 B

    const int tid  = threadIdx.x;
    const int row0 = blockIdx.x * RPT + tid;
    const int row1 = row0 + 128;

    const float sw = g_stat[0], l1wmax = g_stat[1];
    const float s127w = 127.f / sw;

    // ---- per-row prologue: stats, exact L2, window, int8 quantization ----
    float l2[2];
    int   Wint[2];
    int   xp0[16], xp1[16];
#pragma unroll
    for (int r = 0; r < 2; ++r) {
        const int row = r ? row1 : row0;
        int* xp = r ? xp1 : xp0;
        float xr[DIM];
        const float4* src = (const float4*)(X + (size_t)row * DIM);
#pragma unroll
        for (int q = 0; q < 16; ++q) {
            float4 v = src[q];
            xr[q * 4 + 0] = v.x; xr[q * 4 + 1] = v.y;
            xr[q * 4 + 2] = v.z; xr[q * 4 + 3] = v.w;
        }
        float s = 0.f;
#pragma unroll
        for (int d = 0; d < DIM; ++d)
            s = __fadd_rn(s, __fmul_rn(xr[d], xr[d]));
        l2[r] = s;
        float sx = 0.f, l1x = 0.f;
#pragma unroll
        for (int d = 0; d < DIM; ++d) { float a = fabsf(xr[d]); sx = fmaxf(sx, a); l1x += a; }
        sx = fmaxf(sx, 1e-30f);
        const float invsx = sx * (1.f / 127.f), invsw = sw * (1.f / 127.f);
        const float dxm = 0.6f * invsx + 4e-6f * sx;
        const float dwm = 0.6f * invsw + 4e-6f * sw;
        const float c2max = 64.f * sw * sw;
        const float window = 1.5f * (2.f * (dxm * l1wmax + dwm * (l1x * 1.0001f + 64.f * dxm))
                                     + c2max + 1e-6f);
        const float F2 = 2.f * invsx * invsw;
        int wi = (int)ceilf(window / F2) + 2;
        Wint[r] = (wi > (1 << 28)) ? (1 << 28) : wi;
        const float s127x = 127.f / sx;
#pragma unroll
        for (int i = 0; i < 16; ++i) {
            int p = 0;
#pragma unroll
            for (int b = 0; b < 4; ++b) {
                int q = __float2int_rn(xr[i * 4 + b] * s127x);
                q = max(-127, min(127, q));
                p |= (q & 0xff) << (8 * b);
            }
            xp[i] = p;
        }
    }

    float bd0 = 3.4e38f, bd1 = 3.4e38f;
    int   bi0 = 0, bi1 = 0;
    int   rm0 = -(1 << 29), rm1 = -(1 << 29);
    int   th0 = rm0 - Wint[0], th1 = rm1 - Wint[1];
    int   cnt0 = 0, cnt1 = 0;

#define RESCORE(ROW, L2V, BD, BI, JL, CB) do {                               \
        const float* wr_ = wsf + (JL) * WSTR;                                \
        const float* xg_ = X + (size_t)(ROW) * DIM;                          \
        float cl_ = 0.f;                                                     \
        _Pragma("unroll")                                                    \
        for (int d_ = 0; d_ < DIM; ++d_)                                     \
            cl_ = __fmaf_rn(__ldg(xg_ + d_), wr_[d_], cl_);                  \
        float de_ = __fadd_rn(__fsub_rn((L2V), __fmul_rn(2.f, cl_)),         \
                              c2s[JL]);                                      \
        if (de_ < (BD)) { (BD) = de_; (BI) = (CB) + (JL); }                  \
    } while (0)

    const int ntiles = K / NT;
    for (int t = 0; t < ntiles; ++t) {
        const int cb = t * NT;
        __syncthreads();   // prior tile rescores done

        // ---- stage tile: one code per thread. fp32 row + on-the-fly int8 ----
        {
            const int code = tid;
            const float4* src = (const float4*)(W + (size_t)(cb + code) * DIM);
            float4* dstf = (float4*)(wsf + code * WSTR);
            int* dq = wqs + code * 16;
#pragma unroll
            for (int q = 0; q < 16; ++q) {
                float4 v = src[q];
                dstf[q] = v;
                int p0 = __float2int_rn(v.x * s127w); p0 = max(-127, min(127, p0));
                int p1 = __float2int_rn(v.y * s127w); p1 = max(-127, min(127, p1));
                int p2 = __float2int_rn(v.z * s127w); p2 = max(-127, min(127, p2));
                int p3 = __float2int_rn(v.w * s127w); p3 = max(-127, min(127, p3));
                dq[q] = (p0 & 0xff) | ((p1 & 0xff) << 8) | ((p2 & 0xff) << 16)
                      | ((p3 & 0xff) << 24);
            }
            c2s[code] = g_c2[cb + code];
            // pad row 128 (prefetch overrun target) once
            if (t == 0) { int* pz = wqs + 128 * 16; pz[tid & 15] = 0; }
        }
        __syncthreads();

#define DOTS(A0, A1, A2, A3, D0, D1) do {                                    \
        int da0=0, db0=0, dc0=0, dd0=0, da1=0, db1=0, dc1=0, dd1=0;          \
        da0 = dp4a(xp0[0],  (A0).x, da0); db0 = dp4a(xp0[1],  (A0).y, db0);  \
        dc0 = dp4a(xp0[2],  (A0).z, dc0); dd0 = dp4a(xp0[3],  (A0).w, dd0);  \
        da1 = dp4a(xp1[0],  (A0).x, da1); db1 = dp4a(xp1[1],  (A0).y, db1);  \
        dc1 = dp4a(xp1[2],  (A0).z, dc1); dd1 = dp4a(xp1[3],  (A0).w, dd1);  \
        da0 = dp4a(xp0[4],  (A1).x, da0); db0 = dp4a(xp0[5],  (A1).y, db0);  \
        dc0 = dp4a(xp0[6],  (A1).z, dc0); dd0 = dp4a(xp0[7],  (A1).w, dd0);  \
        da1 = dp4a(xp1[4],  (A1).x, da1); db1 = dp4a(xp1[5],  (A1).y, db1);  \
        dc1 = dp4a(xp1[6],  (A1).z, dc1); dd1 = dp4a(xp1[7],  (A1).w, dd1);  \
        da0 = dp4a(xp0[8],  (A2).x, da0); db0 = dp4a(xp0[9],  (A2).y, db0);  \
        dc0 = dp4a(xp0[10], (A2).z, dc0); dd0 = dp4a(xp0[11], (A2).w, dd0);  \
        da1 = dp4a(xp1[8],  (A2).x, da1); db1 = dp4a(xp1[9],  (A2).y, db1);  \
        dc1 = dp4a(xp1[10], (A2).z, dc1); dd1 = dp4a(xp1[11], (A2).w, dd1);  \
        da0 = dp4a(xp0[12], (A3).x, da0); db0 = dp4a(xp0[13], (A3).y, db0);  \
        dc0 = dp4a(xp0[14], (A3).z, dc0); dd0 = dp4a(xp0[15], (A3).w, dd0);  \
        da1 = dp4a(xp1[12], (A3).x, da1); db1 = dp4a(xp1[13], (A3).y, db1);  \
        dc1 = dp4a(xp1[14], (A3).z, dc1); dd1 = dp4a(xp1[15], (A3).w, dd1);  \
        D0 = (da0 + db0) + (dc0 + dd0);                                      \
        D1 = (da1 + db1) + (dc1 + dd1);                                      \
    } while (0)

#define CAND(J, D0, D1) do {                                                 \
        if ((D0) >= th0 || (D1) >= th1) {                                    \
            if ((D0) >= th0) {                                               \
                rm0 = max(rm0, (D0)); th0 = rm0 - Wint[0];                   \
                if (cnt0 == CAP) {                                           \
                    for (int i_ = 0; i_ < cnt0; ++i_) {                      \
                        int jl_ = buf[tid * CAP + i_];                       \
                        RESCORE(row0, l2[0], bd0, bi0, jl_, cb);             \
                    }                                                        \
                    cnt0 = 0;                                                \
                }                                                            \
                buf[tid * CAP + cnt0] = (unsigned short)(J); ++cnt0;         \
            }                                                                \
            if ((D1) >= th1) {                                               \
                rm1 = max(rm1, (D1)); th1 = rm1 - Wint[1];                   \
                if (cnt1 == CAP) {                                           \
                    for (int i_ = 0; i_ < cnt1; ++i_) {                      \
                        int jl_ = buf[(128 + tid) * CAP + i_];               \
                        RESCORE(row1, l2[1], bd1, bi1, jl_, cb);             \
                    }                                                        \
                    cnt1 = 0;                                                \
                }                                                            \
                buf[(128 + tid) * CAP + cnt1] = (unsigned short)(J); ++cnt1; \
            }                                                                \
        }                                                                    \
    } while (0)

        // ---- hot loop: software-pipelined, 2 codes per iteration ----
        {
            const int4* wq4 = (const int4*)wqs;
            int4 a0 = wq4[0], a1 = wq4[1], a2 = wq4[2], a3 = wq4[3];
#pragma unroll 1
            for (int j = 0; j < NT; j += 2) {
                // prefetch j+1 while computing j
                int4 b0 = wq4[(j + 1) * 4 + 0], b1 = wq4[(j + 1) * 4 + 1];
                int4 b2 = wq4[(j + 1) * 4 + 2], b3 = wq4[(j + 1) * 4 + 3];
                int d0, d1;
                DOTS(a0, a1, a2, a3, d0, d1);
                CAND(j, d0, d1);
                // prefetch j+2 (row 128 is zero padding at j=126) while computing j+1
                a0 = wq4[(j + 2) * 4 + 0]; a1 = wq4[(j + 2) * 4 + 1];
                a2 = wq4[(j + 2) * 4 + 2]; a3 = wq4[(j + 2) * 4 + 3];
                DOTS(b0, b1, b2, b3, d0, d1);
                CAND(j + 1, d0, d1);
            }
        }

        // ---- deferred exact rescores (ascending order => first-index ties) ----
        for (int i = 0; i < cnt0; ++i) {
            int jl = buf[tid * CAP + i];
            RESCORE(row0, l2[0], bd0, bi0, jl, cb);
        }
        cnt0 = 0;
        for (int i = 0; i < cnt1; ++i) {
            int jl = buf[(128 + tid) * CAP + i];
            RESCORE(row1, l2[1], bd1, bi1, jl, cb);
        }
        cnt1 = 0;
    }
#undef DOTS
#undef CAND
#undef RESCORE

    // ---- outputs ----
    if (outI) { outI[row0] = (float)bi0; outI[row1] = (float)bi1; }
    if (outQ) {
#pragma unroll
        for (int r = 0; r < 2; ++r) {
            const int row = r ? row1 : row0;
            const int bi  = r ? bi1 : bi0;
            const float4* src = (const float4*)(W + (size_t)bi * DIM);
            float4* dst = (float4*)(outQ + (size_t)row * DIM);
#pragma unroll
            for (int q = 0; q < 16; ++q) dst[q] = __ldg(src + q);
        }
    }
}

// ---------------------------------------------------------------------------
extern "C" void kernel_launch(void* const* d_in, const int* in_sizes, int n_in,
                              void* d_out, int out_size) {
    const float* X = (const float*)d_in[0];
    const float* W = (const float*)d_in[1];
    int N = in_sizes[0] / DIM;
    int K = in_sizes[1] / DIM;

    long long nd = (long long)N * DIM;
    float* outQ = nullptr;
    float* outI = nullptr;
    if ((long long)out_size >= nd + N) { outQ = (float*)d_out; outI = (float*)d_out + nd; }
    else if ((long long)out_size == nd) { outQ = (float*)d_out; }
    else { outI = (float*)d_out; }

    const int smembytes = NT * WSTR * 4 + 129 * 64 + 512 + RPT * CAP * 2; // 49728 B
    cudaFuncSetAttribute(vq_main, cudaFuncAttributeMaxDynamicSharedMemorySize,
                         smembytes);

    prep_kernel<<<1, 1024>>>(W, K);
    vq_main<<<N / RPT, 128, smembytes>>>(X, W, outQ, outI, K);
}